// round 13
// baseline (speedup 1.0000x reference)
#include <cuda_runtime.h>
#include <cstdint>

#define MAXN 50048
#define MAXE 860000

// ---------------- scratch ----------------
__device__ float g_h[MAXN * 128];      // layer1 h (N x 128)
__device__ float g_h2[MAXN * 64];      // layer2 h (N x 64)
__device__ float g_as[MAXN];
__device__ float g_ad[MAXN];
__device__ float g_as2[MAXN];
__device__ float g_ad2[MAXN];
__device__ int   g_deg[MAXN];
__device__ int   g_rank[MAXE];
__device__ int   g_rowptr[MAXN + 1];
__device__ int   g_esorted[MAXE];
__device__ int   g_blocksum[64];

// ---------------- tf32 helpers ----------------
__device__ __forceinline__ uint32_t f2tf32(float f) {
    uint32_t r;
    asm("cvt.rna.tf32.f32 %0, %1;" : "=r"(r) : "f"(f));
    return r;
}
__device__ __forceinline__ void mma_tf32(float& c0, float& c1, float& c2, float& c3,
                                         uint32_t a0, uint32_t a1, uint32_t a2, uint32_t a3,
                                         uint32_t b0, uint32_t b1) {
    asm("mma.sync.aligned.m16n8k8.row.col.f32.tf32.tf32.f32 "
        "{%0,%1,%2,%3}, {%4,%5,%6,%7}, {%8,%9}, {%0,%1,%2,%3};"
        : "+f"(c0), "+f"(c1), "+f"(c2), "+f"(c3)
        : "r"(a0), "r"(a1), "r"(a2), "r"(a3), "r"(b0), "r"(b1));
}

// ---------------- tf32 GEMM1 (+alpha1 epilogue) ----------------
// C[M,128] = A[M,K] @ B[K,128].  BM=128, BK=16, 256 threads (8 warps, 4m x 2n).
__global__ void gemm_mma_alpha_kernel(const float* __restrict__ A, const float* __restrict__ B,
                                      float* __restrict__ C,
                                      const float* __restrict__ avs, const float* __restrict__ avd,
                                      int M, int K) {
    constexpr int BN = 128;
    constexpr int NSUB = 8;
    __shared__ float As[128][20];
    __shared__ float Bs[BN][20];
    __shared__ float shA[2][128];
    __shared__ float shD[2][128];

    const int tid = threadIdx.x;
    const int wid = tid >> 5;
    const int lane = tid & 31;
    const int g = lane >> 2;
    const int tg = lane & 3;
    const int wm = wid >> 1;
    const int wn = wid & 1;
    const int bm = blockIdx.x * 128;
    const int nbase = wn * 64;

    float acc[2][NSUB][4];
#pragma unroll
    for (int mi = 0; mi < 2; mi++)
#pragma unroll
        for (int ni = 0; ni < NSUB; ni++)
#pragma unroll
            for (int r = 0; r < 4; r++) acc[mi][ni][r] = 0.0f;

    for (int k0 = 0; k0 < K; k0 += 16) {
#pragma unroll
        for (int p = 0; p < 2; p++) {
            int fid = tid + p * 256;
            int row = fid >> 2;
            int ko = (fid & 3) * 4;
            float4 v = make_float4(0.f, 0.f, 0.f, 0.f);
            if (bm + row < M) v = *reinterpret_cast<const float4*>(&A[(size_t)(bm + row) * K + k0 + ko]);
            *reinterpret_cast<float4*>(&As[row][ko]) = v;
        }
#pragma unroll
        for (int p = 0; p < 2; p++) {
            int fid = tid + p * 256;
            int k = fid >> 5;
            int nf = (fid & 31) * 4;
            float4 v = *reinterpret_cast<const float4*>(&B[(size_t)(k0 + k) * BN + nf]);
            Bs[nf + 0][k] = v.x;
            Bs[nf + 1][k] = v.y;
            Bs[nf + 2][k] = v.z;
            Bs[nf + 3][k] = v.w;
        }
        __syncthreads();
#pragma unroll
        for (int ks = 0; ks < 2; ks++) {
            const int kb = ks * 8;
            uint32_t af[2][4];
#pragma unroll
            for (int mi = 0; mi < 2; mi++) {
                int row = wm * 32 + mi * 16 + g;
                af[mi][0] = f2tf32(As[row][kb + tg]);
                af[mi][1] = f2tf32(As[row + 8][kb + tg]);
                af[mi][2] = f2tf32(As[row][kb + tg + 4]);
                af[mi][3] = f2tf32(As[row + 8][kb + tg + 4]);
            }
#pragma unroll
            for (int ni = 0; ni < NSUB; ni++) {
                int nrow = nbase + ni * 8 + g;
                uint32_t b0 = f2tf32(Bs[nrow][kb + tg]);
                uint32_t b1 = f2tf32(Bs[nrow][kb + tg + 4]);
#pragma unroll
                for (int mi = 0; mi < 2; mi++)
                    mma_tf32(acc[mi][ni][0], acc[mi][ni][1], acc[mi][ni][2], acc[mi][ni][3],
                             af[mi][0], af[mi][1], af[mi][2], af[mi][3], b0, b1);
            }
        }
        __syncthreads();
    }

    float2 av2[NSUB], dv2[NSUB];
#pragma unroll
    for (int ni = 0; ni < NSUB; ni++) {
        int col = nbase + ni * 8 + tg * 2;
        av2[ni] = *reinterpret_cast<const float2*>(&avs[col]);
        dv2[ni] = *reinterpret_cast<const float2*>(&avd[col]);
    }

#pragma unroll
    for (int mi = 0; mi < 2; mi++) {
        float s0 = 0.f, d0 = 0.f, s1 = 0.f, d1 = 0.f;
        int row = bm + wm * 32 + mi * 16 + g;
#pragma unroll
        for (int ni = 0; ni < NSUB; ni++) {
            int col = nbase + ni * 8 + tg * 2;
            if (row < M)
                *reinterpret_cast<float2*>(&C[(size_t)row * BN + col]) =
                    make_float2(acc[mi][ni][0], acc[mi][ni][1]);
            if (row + 8 < M)
                *reinterpret_cast<float2*>(&C[(size_t)(row + 8) * BN + col]) =
                    make_float2(acc[mi][ni][2], acc[mi][ni][3]);
            s0 = fmaf(acc[mi][ni][0], av2[ni].x, fmaf(acc[mi][ni][1], av2[ni].y, s0));
            d0 = fmaf(acc[mi][ni][0], dv2[ni].x, fmaf(acc[mi][ni][1], dv2[ni].y, d0));
            s1 = fmaf(acc[mi][ni][2], av2[ni].x, fmaf(acc[mi][ni][3], av2[ni].y, s1));
            d1 = fmaf(acc[mi][ni][2], dv2[ni].x, fmaf(acc[mi][ni][3], dv2[ni].y, d1));
        }
#pragma unroll
        for (int o = 1; o <= 2; o <<= 1) {
            s0 += __shfl_xor_sync(0xffffffffu, s0, o);
            d0 += __shfl_xor_sync(0xffffffffu, d0, o);
            s1 += __shfl_xor_sync(0xffffffffu, s1, o);
            d1 += __shfl_xor_sync(0xffffffffu, d1, o);
        }
        if (tg == 0) {
            int lr = wm * 32 + mi * 16 + g;
            shA[wn][lr] = s0;
            shD[wn][lr] = d0;
            shA[wn][lr + 8] = s1;
            shD[wn][lr + 8] = d1;
        }
    }
    __syncthreads();
    if (tid < 128 && bm + tid < M) {
        g_as[bm + tid] = shA[0][tid] + shA[1][tid];
        g_ad[bm + tid] = shD[0][tid] + shD[1][tid];
    }
}

// ---------------- hist + rank, 4 edges per thread ----------------
__global__ void hist_kernel(const int* __restrict__ dst, int E, int ET) {
    int t = blockIdx.x * blockDim.x + threadIdx.x;
    int nv = E >> 2;
    if (t < nv) {
        int4 d4 = reinterpret_cast<const int4*>(dst)[t];
        int4 r4;
        r4.x = atomicAdd(&g_deg[d4.x], 1);
        r4.y = atomicAdd(&g_deg[d4.y], 1);
        r4.z = atomicAdd(&g_deg[d4.z], 1);
        r4.w = atomicAdd(&g_deg[d4.w], 1);
        *reinterpret_cast<int4*>(&g_rank[t * 4]) = r4;
    } else {
        int i = (E & ~3) + (t - nv);
        if (i < ET) {
            int d = (i < E) ? __ldg(&dst[i]) : (i - E);
            g_rank[i] = atomicAdd(&g_deg[d], 1);
        }
    }
}

// ---------------- scans ----------------
__global__ void scan_partial_kernel(int N) {
    __shared__ int wsum[32];
    int t = threadIdx.x;
    int i = blockIdx.x * 1024 + t;
    int v = (i < N) ? g_deg[i] : 0;
#pragma unroll
    for (int o = 16; o > 0; o >>= 1) v += __shfl_xor_sync(0xffffffffu, v, o);
    if ((t & 31) == 0) wsum[t >> 5] = v;
    __syncthreads();
    if (t < 32) {
        int x = wsum[t];
#pragma unroll
        for (int o = 16; o > 0; o >>= 1) x += __shfl_xor_sync(0xffffffffu, x, o);
        if (t == 0) g_blocksum[blockIdx.x] = x;
    }
}

__global__ void scan_final_kernel(int N, int nb) {
    __shared__ int wsum[32];
    __shared__ int bsm[64];
    __shared__ int base_sh;
    int t = threadIdx.x;
    int lane = t & 31;
    int wid = t >> 5;
    int i = blockIdx.x * 1024 + t;
    int v = (i < N) ? g_deg[i] : 0;
    int x = v;
#pragma unroll
    for (int o = 1; o < 32; o <<= 1) {
        int y = __shfl_up_sync(0xffffffffu, x, o);
        if (lane >= o) x += y;
    }
    if (lane == 31) wsum[wid] = x;
    if (t < nb) bsm[t] = g_blocksum[t];
    __syncthreads();
    if (t < 32) {
        int w = wsum[t];
#pragma unroll
        for (int o = 1; o < 32; o <<= 1) {
            int y = __shfl_up_sync(0xffffffffu, w, o);
            if (t >= o) w += y;
        }
        wsum[t] = w;
    }
    if (t == 0) {
        int s = 0;
        for (int j = 0; j < blockIdx.x; j++) s += bsm[j];
        base_sh = s;
        if (blockIdx.x == 0) {
            int tot = 0;
            for (int j = 0; j < nb; j++) tot += bsm[j];
            g_rowptr[N] = tot;
        }
    }
    __syncthreads();
    int incl = x + ((wid > 0) ? wsum[wid - 1] : 0);
    int excl = base_sh + incl - v;
    if (i < N) g_rowptr[i] = excl;
}

// ---------------- fill: no atomics ----------------
__global__ void fill_kernel(const int* __restrict__ src, const int* __restrict__ dst,
                            int E, int ET) {
    int t = blockIdx.x * blockDim.x + threadIdx.x;
    int nv = E >> 2;
    if (t < nv) {
        int4 s4 = reinterpret_cast<const int4*>(src)[t];
        int4 d4 = reinterpret_cast<const int4*>(dst)[t];
        int4 r4 = *reinterpret_cast<const int4*>(&g_rank[t * 4]);
        g_esorted[g_rowptr[d4.x] + r4.x] = s4.x;
        g_esorted[g_rowptr[d4.y] + r4.y] = s4.y;
        g_esorted[g_rowptr[d4.z] + r4.z] = s4.z;
        g_esorted[g_rowptr[d4.w] + r4.w] = s4.w;
    } else {
        int i = (E & ~3) + (t - nv);
        if (i < ET) {
            int s, d;
            if (i < E) { s = __ldg(&src[i]); d = __ldg(&dst[i]); }
            else       { s = d = i - E; }
            g_esorted[g_rowptr[d] + g_rank[i]] = s;
        }
    }
}

// ---------------- FUSED: gather layer1 (softmax-agg, relu, bias) into smem + GEMM2 + alpha2 ----------------
// Block = 64 dst nodes, 256 threads (8 warps). Phase A: each warp gathers 8 nodes.
// Phase B: C[64,64] = As[64,128] @ W2[128,64], tf32 mma; h2 + alpha2 epilogue.
__global__ void gather_gemm2_kernel(const float* __restrict__ h,
                                    const float* __restrict__ b1,
                                    const float* __restrict__ W2,
                                    const float* __restrict__ avs,
                                    const float* __restrict__ avd,
                                    float* __restrict__ h2, int N) {
    __shared__ float As[64][132];   // x2 rows (fp32)
    __shared__ float Bs[64][20];    // W2 k-tile, [n][k]
    __shared__ float shA[2][64];
    __shared__ float shD[2][64];

    const int tid = threadIdx.x;
    const int wid = tid >> 5;
    const int lane = tid & 31;
    const int bm = blockIdx.x * 64;

    // ---------- Phase A: gather 8 nodes per warp ----------
    {
        const float4* h4 = reinterpret_cast<const float4*>(h);
        float4 b4 = reinterpret_cast<const float4*>(b1)[lane];
        for (int r = 0; r < 8; r++) {
            int lrow = wid * 8 + r;
            int d = bm + lrow;
            if (d >= N) break;
            int start = g_rowptr[d];
            int end = g_rowptr[d + 1];
            float ad = g_ad[d];
            float4 acc = make_float4(0.f, 0.f, 0.f, 0.f);
            float den = 0.0f;
            for (int e0 = start; e0 < end; e0 += 32) {
                int mye = e0 + lane;
                float w = 0.0f;
                int s = 0;
                if (mye < end) {
                    s = g_esorted[mye];
                    float sc = g_as[s] + ad;
                    sc = (sc >= 0.0f) ? sc : 0.2f * sc;
                    w = __expf(sc);
                }
                den += w;
                int cnt = min(32, end - e0);
                for (int j = 0; j < cnt; j++) {
                    float wj = __shfl_sync(0xffffffffu, w, j);
                    int sj = __shfl_sync(0xffffffffu, s, j);
                    float4 hv = h4[(size_t)sj * 32 + lane];
                    acc.x = fmaf(wj, hv.x, acc.x);
                    acc.y = fmaf(wj, hv.y, acc.y);
                    acc.z = fmaf(wj, hv.z, acc.z);
                    acc.w = fmaf(wj, hv.w, acc.w);
                }
            }
#pragma unroll
            for (int o = 16; o > 0; o >>= 1) den += __shfl_xor_sync(0xffffffffu, den, o);
            float rc = __frcp_rn(den);
            float4 v;
            v.x = fmaxf(fmaf(acc.x, rc, b4.x), 0.f);
            v.y = fmaxf(fmaf(acc.y, rc, b4.y), 0.f);
            v.z = fmaxf(fmaf(acc.z, rc, b4.z), 0.f);
            v.w = fmaxf(fmaf(acc.w, rc, b4.w), 0.f);
            *reinterpret_cast<float4*>(&As[lrow][lane * 4]) = v;
        }
    }
    __syncthreads();

    // ---------- Phase B: GEMM 64x64x128 (tf32) ----------
    const int g = lane >> 2;
    const int tg = lane & 3;
    const int wm = wid >> 1;        // 0..3 -> m16 tile
    const int wn = wid & 1;         // 0..1 -> 32-col half
    constexpr int NSUB = 4;

    float acc[NSUB][4];
#pragma unroll
    for (int ni = 0; ni < NSUB; ni++)
#pragma unroll
        for (int r = 0; r < 4; r++) acc[ni][r] = 0.0f;

    for (int k0 = 0; k0 < 128; k0 += 16) {
        {
            int k = tid >> 4;
            int nf = (tid & 15) * 4;
            float4 v = *reinterpret_cast<const float4*>(&W2[(size_t)(k0 + k) * 64 + nf]);
            Bs[nf + 0][k] = v.x;
            Bs[nf + 1][k] = v.y;
            Bs[nf + 2][k] = v.z;
            Bs[nf + 3][k] = v.w;
        }
        __syncthreads();
#pragma unroll
        for (int ks = 0; ks < 2; ks++) {
            const int kb = ks * 8;
            int row = wm * 16 + g;
            uint32_t a0 = f2tf32(As[row][k0 + kb + tg]);
            uint32_t a1 = f2tf32(As[row + 8][k0 + kb + tg]);
            uint32_t a2 = f2tf32(As[row][k0 + kb + tg + 4]);
            uint32_t a3 = f2tf32(As[row + 8][k0 + kb + tg + 4]);
#pragma unroll
            for (int ni = 0; ni < NSUB; ni++) {
                int nrow = wn * 32 + ni * 8 + g;
                uint32_t b0 = f2tf32(Bs[nrow][kb + tg]);
                uint32_t bb1 = f2tf32(Bs[nrow][kb + tg + 4]);
                mma_tf32(acc[ni][0], acc[ni][1], acc[ni][2], acc[ni][3],
                         a0, a1, a2, a3, b0, bb1);
            }
        }
        __syncthreads();
    }

    // epilogue: store h2 + alpha2
    float2 av2[NSUB], dv2[NSUB];
#pragma unroll
    for (int ni = 0; ni < NSUB; ni++) {
        int col = wn * 32 + ni * 8 + tg * 2;
        av2[ni] = *reinterpret_cast<const float2*>(&avs[col]);
        dv2[ni] = *reinterpret_cast<const float2*>(&avd[col]);
    }
    {
        float s0 = 0.f, d0 = 0.f, s1 = 0.f, d1 = 0.f;
        int row = bm + wm * 16 + g;
#pragma unroll
        for (int ni = 0; ni < NSUB; ni++) {
            int col = wn * 32 + ni * 8 + tg * 2;
            if (row < N)
                *reinterpret_cast<float2*>(&h2[(size_t)row * 64 + col]) =
                    make_float2(acc[ni][0], acc[ni][1]);
            if (row + 8 < N)
                *reinterpret_cast<float2*>(&h2[(size_t)(row + 8) * 64 + col]) =
                    make_float2(acc[ni][2], acc[ni][3]);
            s0 = fmaf(acc[ni][0], av2[ni].x, fmaf(acc[ni][1], av2[ni].y, s0));
            d0 = fmaf(acc[ni][0], dv2[ni].x, fmaf(acc[ni][1], dv2[ni].y, d0));
            s1 = fmaf(acc[ni][2], av2[ni].x, fmaf(acc[ni][3], av2[ni].y, s1));
            d1 = fmaf(acc[ni][2], dv2[ni].x, fmaf(acc[ni][3], dv2[ni].y, d1));
        }
#pragma unroll
        for (int o = 1; o <= 2; o <<= 1) {
            s0 += __shfl_xor_sync(0xffffffffu, s0, o);
            d0 += __shfl_xor_sync(0xffffffffu, d0, o);
            s1 += __shfl_xor_sync(0xffffffffu, s1, o);
            d1 += __shfl_xor_sync(0xffffffffu, d1, o);
        }
        if (tg == 0) {
            int lr = wm * 16 + g;
            shA[wn][lr] = s0;
            shD[wn][lr] = d0;
            shA[wn][lr + 8] = s1;
            shD[wn][lr + 8] = d1;
        }
    }
    __syncthreads();
    if (tid < 64 && bm + tid < N) {
        g_as2[bm + tid] = shA[0][tid] + shA[1][tid];
        g_ad2[bm + tid] = shD[0][tid] + shD[1][tid];
    }
}

// ---------------- gather layer 2: per-dst 16-lane group, fused softmax+agg+bias ----------------
__global__ void gather2_kernel(const float* __restrict__ h,
                               const float* __restrict__ gas,
                               const float* __restrict__ gad,
                               const float* __restrict__ bias,
                               float* __restrict__ out, int N) {
    constexpr int F4 = 16;
    int warp = (blockIdx.x * blockDim.x + threadIdx.x) >> 5;
    int lane = threadIdx.x & 31;
    int sub = lane >> 4;
    int li = lane & 15;
    int d = warp * 2 + sub;
    const unsigned gmask = 0xffffu << (sub * 16);
    const int base = sub * 16;

    int start = 0, end = 0;
    float ad = 0.0f;
    if (d < N) {
        start = g_rowptr[d];
        end = g_rowptr[d + 1];
        ad = gad[d];
    }

    float4 acc = make_float4(0.f, 0.f, 0.f, 0.f);
    float den = 0.0f;
    const float4* h4 = reinterpret_cast<const float4*>(h);

    for (int e0 = start; e0 < end; e0 += F4) {
        int mye = e0 + li;
        float w = 0.0f;
        int s = 0;
        if (mye < end) {
            s = g_esorted[mye];
            float sc = gas[s] + ad;
            sc = (sc >= 0.0f) ? sc : 0.2f * sc;
            w = __expf(sc);
        }
        den += w;
        int cnt = min(F4, end - e0);
        for (int j = 0; j < cnt; j++) {
            float wj = __shfl_sync(gmask, w, base + j);
            int sj = __shfl_sync(gmask, s, base + j);
            float4 hv = h4[(size_t)sj * F4 + li];
            acc.x = fmaf(wj, hv.x, acc.x);
            acc.y = fmaf(wj, hv.y, acc.y);
            acc.z = fmaf(wj, hv.z, acc.z);
            acc.w = fmaf(wj, hv.w, acc.w);
        }
    }
#pragma unroll
    for (int o = 8; o > 0; o >>= 1) den += __shfl_xor_sync(gmask, den, o);

    if (d < N) {
        float r = __frcp_rn(den);
        float4 b4 = reinterpret_cast<const float4*>(bias)[li];
        float4 v;
        v.x = fmaf(acc.x, r, b4.x);
        v.y = fmaf(acc.y, r, b4.y);
        v.z = fmaf(acc.z, r, b4.z);
        v.w = fmaf(acc.w, r, b4.w);
        reinterpret_cast<float4*>(out)[(size_t)d * F4 + li] = v;
    }
}

// ---------------- launch ----------------
extern "C" void kernel_launch(void* const* d_in, const int* in_sizes, int n_in,
                              void* d_out, int out_size) {
    const float* X     = (const float*)d_in[0];
    const int*   EI    = (const int*)d_in[1];
    const float* W1    = (const float*)d_in[2];
    const float* asrc1 = (const float*)d_in[3];
    const float* adst1 = (const float*)d_in[4];
    const float* b1    = (const float*)d_in[5];
    const float* W2    = (const float*)d_in[6];
    const float* asrc2 = (const float*)d_in[7];
    const float* adst2 = (const float*)d_in[8];
    const float* b2    = (const float*)d_in[9];
    float* out = (float*)d_out;

    const int F_IN = 128;
    const int N = in_sizes[0] / F_IN;
    const int E = in_sizes[1] / 2;
    const int ET = E + N;
    const int* src = EI;
    const int* dst = EI + E;

    float *p_h, *p_h2, *p_as2, *p_ad2;
    int *p_deg;
    cudaGetSymbolAddress((void**)&p_h, g_h);
    cudaGetSymbolAddress((void**)&p_h2, g_h2);
    cudaGetSymbolAddress((void**)&p_as2, g_as2);
    cudaGetSymbolAddress((void**)&p_ad2, g_ad2);
    cudaGetSymbolAddress((void**)&p_deg, g_deg);

    const int BT = 256;
    const int nb = (N + 1023) / 1024;
    const int gB1 = (N + 127) / 128;

    static cudaStream_t s2 = nullptr;
    static cudaEvent_t evFork = nullptr, evJoin = nullptr;
    if (s2 == nullptr) {
        cudaStreamCreateWithFlags(&s2, cudaStreamNonBlocking);
        cudaEventCreateWithFlags(&evFork, cudaEventDisableTiming);
        cudaEventCreateWithFlags(&evJoin, cudaEventDisableTiming);
    }

    // ---- fork: CSR build on s2, GEMM1 on main stream ----
    cudaEventRecord(evFork, 0);
    cudaStreamWaitEvent(s2, evFork, 0);

    cudaMemsetAsync(p_deg, 0, (size_t)N * sizeof(int), s2);
    {
        int histT = (E >> 2) + (ET - (E & ~3));
        hist_kernel<<<(histT + BT - 1) / BT, BT, 0, s2>>>(dst, E, ET);
    }
    scan_partial_kernel<<<nb, 1024, 0, s2>>>(N);
    scan_final_kernel<<<nb, 1024, 0, s2>>>(N, nb);
    {
        int fillT = (E >> 2) + (ET - (E & ~3));
        fill_kernel<<<(fillT + BT - 1) / BT, BT, 0, s2>>>(src, dst, E, ET);
    }
    cudaEventRecord(evJoin, s2);

    // GEMM1 (+alpha1), tensor cores, concurrent with CSR build
    gemm_mma_alpha_kernel<<<gB1, BT>>>(X, W1, p_h, asrc1, adst1, N, F_IN);

    // ---- join ----
    cudaStreamWaitEvent(0, evJoin, 0);

    // fused: gather layer1 (smem) + GEMM2 + alpha2
    gather_gemm2_kernel<<<(N + 63) / 64, BT>>>(p_h, b1, W2, asrc2, adst2, p_h2, N);

    // gather layer 2 -> out
    {
        long warps = (N + 1) / 2;
        gather2_kernel<<<(unsigned)((warps * 32 + BT - 1) / BT), BT>>>(p_h2, p_as2, p_ad2, b2, out, N);
    }
}

// round 14
// speedup vs baseline: 1.0940x; 1.0940x over previous
#include <cuda_runtime.h>
#include <cstdint>

#define MAXN 50048
#define MAXE 860000

// ---------------- scratch ----------------
__device__ float g_h[MAXN * 128];
__device__ float g_x2[MAXN * 128];
__device__ float g_as[MAXN];
__device__ float g_ad[MAXN];
__device__ int   g_deg[MAXN];
__device__ int   g_rank[MAXE];
__device__ int   g_rowptr[MAXN + 1];
__device__ int   g_esorted[MAXE];
__device__ int   g_blocksum[64];

// ---------------- tf32 helpers ----------------
__device__ __forceinline__ uint32_t f2tf32(float f) {
    uint32_t r;
    asm("cvt.rna.tf32.f32 %0, %1;" : "=r"(r) : "f"(f));
    return r;
}
__device__ __forceinline__ void mma_tf32(float& c0, float& c1, float& c2, float& c3,
                                         uint32_t a0, uint32_t a1, uint32_t a2, uint32_t a3,
                                         uint32_t b0, uint32_t b1) {
    asm("mma.sync.aligned.m16n8k8.row.col.f32.tf32.tf32.f32 "
        "{%0,%1,%2,%3}, {%4,%5,%6,%7}, {%8,%9}, {%0,%1,%2,%3};"
        : "+f"(c0), "+f"(c1), "+f"(c2), "+f"(c3)
        : "r"(a0), "r"(a1), "r"(a2), "r"(a3), "r"(b0), "r"(b1));
}

// ---------------- tf32 tensor-core GEMM (+alpha epilogue) ----------------
// C[M,BN] = A[M,K] @ B[K,BN].  BM=128, BK=16, 256 threads (8 warps, 4m x 2n).
// smem holds tf32-converted values (convert once at store).
template <int BN>
__global__ void gemm_mma_alpha_kernel(const float* __restrict__ A, const float* __restrict__ B,
                                      float* __restrict__ C,
                                      const float* __restrict__ avs, const float* __restrict__ avd,
                                      int M, int K) {
    constexpr int NSUB = BN / 16;
    __shared__ uint32_t As[128][20];
    __shared__ uint32_t Bs[BN][20];
    __shared__ float shA[2][128];
    __shared__ float shD[2][128];

    const int tid = threadIdx.x;
    const int wid = tid >> 5;
    const int lane = tid & 31;
    const int g = lane >> 2;
    const int tg = lane & 3;
    const int wm = wid >> 1;
    const int wn = wid & 1;
    const int bm = blockIdx.x * 128;
    const int nbase = wn * (BN / 2);

    float acc[2][NSUB][4];
#pragma unroll
    for (int mi = 0; mi < 2; mi++)
#pragma unroll
        for (int ni = 0; ni < NSUB; ni++)
#pragma unroll
            for (int r = 0; r < 4; r++) acc[mi][ni][r] = 0.0f;

    for (int k0 = 0; k0 < K; k0 += 16) {
#pragma unroll
        for (int p = 0; p < 2; p++) {
            int fid = tid + p * 256;
            int row = fid >> 2;
            int ko = (fid & 3) * 4;
            float4 v = make_float4(0.f, 0.f, 0.f, 0.f);
            if (bm + row < M) v = *reinterpret_cast<const float4*>(&A[(size_t)(bm + row) * K + k0 + ko]);
            As[row][ko + 0] = f2tf32(v.x);
            As[row][ko + 1] = f2tf32(v.y);
            As[row][ko + 2] = f2tf32(v.z);
            As[row][ko + 3] = f2tf32(v.w);
        }
#pragma unroll
        for (int p = 0; p < BN / 64; p++) {
            int fid = tid + p * 256;
            int k = fid / (BN / 4);
            int nf = (fid % (BN / 4)) * 4;
            float4 v = *reinterpret_cast<const float4*>(&B[(size_t)(k0 + k) * BN + nf]);
            Bs[nf + 0][k] = f2tf32(v.x);
            Bs[nf + 1][k] = f2tf32(v.y);
            Bs[nf + 2][k] = f2tf32(v.z);
            Bs[nf + 3][k] = f2tf32(v.w);
        }
        __syncthreads();
#pragma unroll
        for (int ks = 0; ks < 2; ks++) {
            const int kb = ks * 8;
            uint32_t af[2][4];
#pragma unroll
            for (int mi = 0; mi < 2; mi++) {
                int row = wm * 32 + mi * 16 + g;
                af[mi][0] = As[row][kb + tg];
                af[mi][1] = As[row + 8][kb + tg];
                af[mi][2] = As[row][kb + tg + 4];
                af[mi][3] = As[row + 8][kb + tg + 4];
            }
#pragma unroll
            for (int ni = 0; ni < NSUB; ni++) {
                int nrow = nbase + ni * 8 + g;
                uint32_t b0 = Bs[nrow][kb + tg];
                uint32_t b1 = Bs[nrow][kb + tg + 4];
#pragma unroll
                for (int mi = 0; mi < 2; mi++)
                    mma_tf32(acc[mi][ni][0], acc[mi][ni][1], acc[mi][ni][2], acc[mi][ni][3],
                             af[mi][0], af[mi][1], af[mi][2], af[mi][3], b0, b1);
            }
        }
        __syncthreads();
    }

    float2 av2[NSUB], dv2[NSUB];
#pragma unroll
    for (int ni = 0; ni < NSUB; ni++) {
        int col = nbase + ni * 8 + tg * 2;
        av2[ni] = *reinterpret_cast<const float2*>(&avs[col]);
        dv2[ni] = *reinterpret_cast<const float2*>(&avd[col]);
    }

#pragma unroll
    for (int mi = 0; mi < 2; mi++) {
        float s0 = 0.f, d0 = 0.f, s1 = 0.f, d1 = 0.f;
        int row = bm + wm * 32 + mi * 16 + g;
#pragma unroll
        for (int ni = 0; ni < NSUB; ni++) {
            int col = nbase + ni * 8 + tg * 2;
            if (row < M)
                *reinterpret_cast<float2*>(&C[(size_t)row * BN + col]) =
                    make_float2(acc[mi][ni][0], acc[mi][ni][1]);
            if (row + 8 < M)
                *reinterpret_cast<float2*>(&C[(size_t)(row + 8) * BN + col]) =
                    make_float2(acc[mi][ni][2], acc[mi][ni][3]);
            s0 = fmaf(acc[mi][ni][0], av2[ni].x, fmaf(acc[mi][ni][1], av2[ni].y, s0));
            d0 = fmaf(acc[mi][ni][0], dv2[ni].x, fmaf(acc[mi][ni][1], dv2[ni].y, d0));
            s1 = fmaf(acc[mi][ni][2], av2[ni].x, fmaf(acc[mi][ni][3], av2[ni].y, s1));
            d1 = fmaf(acc[mi][ni][2], dv2[ni].x, fmaf(acc[mi][ni][3], dv2[ni].y, d1));
        }
#pragma unroll
        for (int o = 1; o <= 2; o <<= 1) {
            s0 += __shfl_xor_sync(0xffffffffu, s0, o);
            d0 += __shfl_xor_sync(0xffffffffu, d0, o);
            s1 += __shfl_xor_sync(0xffffffffu, s1, o);
            d1 += __shfl_xor_sync(0xffffffffu, d1, o);
        }
        if (tg == 0) {
            int lr = wm * 32 + mi * 16 + g;
            shA[wn][lr] = s0;
            shD[wn][lr] = d0;
            shA[wn][lr + 8] = s1;
            shD[wn][lr + 8] = d1;
        }
    }
    __syncthreads();
    if (tid < 128 && bm + tid < M) {
        g_as[bm + tid] = shA[0][tid] + shA[1][tid];
        g_ad[bm + tid] = shD[0][tid] + shD[1][tid];
    }
}

// ---------------- hist + rank, 4 edges per thread ----------------
__global__ void hist_kernel(const int* __restrict__ dst, int E, int ET) {
    int t = blockIdx.x * blockDim.x + threadIdx.x;
    int nv = E >> 2;
    if (t < nv) {
        int4 d4 = reinterpret_cast<const int4*>(dst)[t];
        int4 r4;
        r4.x = atomicAdd(&g_deg[d4.x], 1);
        r4.y = atomicAdd(&g_deg[d4.y], 1);
        r4.z = atomicAdd(&g_deg[d4.z], 1);
        r4.w = atomicAdd(&g_deg[d4.w], 1);
        *reinterpret_cast<int4*>(&g_rank[t * 4]) = r4;
    } else {
        int i = (E & ~3) + (t - nv);
        if (i < ET) {
            int d = (i < E) ? __ldg(&dst[i]) : (i - E);
            g_rank[i] = atomicAdd(&g_deg[d], 1);
        }
    }
}

// ---------------- scans ----------------
__global__ void scan_partial_kernel(int N) {
    __shared__ int wsum[32];
    int t = threadIdx.x;
    int i = blockIdx.x * 1024 + t;
    int v = (i < N) ? g_deg[i] : 0;
#pragma unroll
    for (int o = 16; o > 0; o >>= 1) v += __shfl_xor_sync(0xffffffffu, v, o);
    if ((t & 31) == 0) wsum[t >> 5] = v;
    __syncthreads();
    if (t < 32) {
        int x = wsum[t];
#pragma unroll
        for (int o = 16; o > 0; o >>= 1) x += __shfl_xor_sync(0xffffffffu, x, o);
        if (t == 0) g_blocksum[blockIdx.x] = x;
    }
}

__global__ void scan_final_kernel(int N, int nb) {
    __shared__ int wsum[32];
    __shared__ int bsm[64];
    __shared__ int base_sh;
    int t = threadIdx.x;
    int lane = t & 31;
    int wid = t >> 5;
    int i = blockIdx.x * 1024 + t;
    int v = (i < N) ? g_deg[i] : 0;
    int x = v;
#pragma unroll
    for (int o = 1; o < 32; o <<= 1) {
        int y = __shfl_up_sync(0xffffffffu, x, o);
        if (lane >= o) x += y;
    }
    if (lane == 31) wsum[wid] = x;
    if (t < nb) bsm[t] = g_blocksum[t];
    __syncthreads();
    if (t < 32) {
        int w = wsum[t];
#pragma unroll
        for (int o = 1; o < 32; o <<= 1) {
            int y = __shfl_up_sync(0xffffffffu, w, o);
            if (t >= o) w += y;
        }
        wsum[t] = w;
    }
    if (t == 0) {
        int s = 0;
        for (int j = 0; j < blockIdx.x; j++) s += bsm[j];
        base_sh = s;
        if (blockIdx.x == 0) {
            int tot = 0;
            for (int j = 0; j < nb; j++) tot += bsm[j];
            g_rowptr[N] = tot;
        }
    }
    __syncthreads();
    int incl = x + ((wid > 0) ? wsum[wid - 1] : 0);
    int excl = base_sh + incl - v;
    if (i < N) g_rowptr[i] = excl;
}

// ---------------- fill: no atomics, 4 edges per thread ----------------
__global__ void fill_kernel(const int* __restrict__ src, const int* __restrict__ dst,
                            int E, int ET) {
    int t = blockIdx.x * blockDim.x + threadIdx.x;
    int nv = E >> 2;
    if (t < nv) {
        int4 s4 = reinterpret_cast<const int4*>(src)[t];
        int4 d4 = reinterpret_cast<const int4*>(dst)[t];
        int4 r4 = *reinterpret_cast<const int4*>(&g_rank[t * 4]);
        g_esorted[g_rowptr[d4.x] + r4.x] = s4.x;
        g_esorted[g_rowptr[d4.y] + r4.y] = s4.y;
        g_esorted[g_rowptr[d4.z] + r4.z] = s4.z;
        g_esorted[g_rowptr[d4.w] + r4.w] = s4.w;
    } else {
        int i = (E & ~3) + (t - nv);
        if (i < ET) {
            int s, d;
            if (i < E) { s = __ldg(&src[i]); d = __ldg(&dst[i]); }
            else       { s = d = i - E; }
            g_esorted[g_rowptr[d] + g_rank[i]] = s;
        }
    }
}

// ---------------- gather: per-dst lane-group, fused softmax+agg+bias(+relu) ----------------
template <int F4, bool RELU>
__global__ void gather_kernel(const float* __restrict__ h,
                              const float* __restrict__ bias,
                              float* __restrict__ out, int N) {
    constexpr int NPW = 32 / F4;
    int warp = (blockIdx.x * blockDim.x + threadIdx.x) >> 5;
    int lane = threadIdx.x & 31;
    int sub = lane / F4;
    int li = lane % F4;
    int d = warp * NPW + sub;
    const unsigned gmask = ((F4 == 32) ? 0xffffffffu : ((1u << F4) - 1u) << (sub * F4));
    const int base = sub * F4;

    int start = 0, end = 0;
    float ad = 0.0f;
    if (d < N) {
        start = g_rowptr[d];
        end = g_rowptr[d + 1];
        ad = g_ad[d];
    }

    float4 acc = make_float4(0.f, 0.f, 0.f, 0.f);
    float den = 0.0f;
    const float4* h4 = reinterpret_cast<const float4*>(h);

    for (int e0 = start; e0 < end; e0 += F4) {
        int mye = e0 + li;
        float w = 0.0f;
        int s = 0;
        if (mye < end) {
            s = g_esorted[mye];
            float sc = g_as[s] + ad;
            sc = (sc >= 0.0f) ? sc : 0.2f * sc;
            w = __expf(sc);
        }
        den += w;
        int cnt = min(F4, end - e0);
        for (int j = 0; j < cnt; j++) {
            float wj = __shfl_sync(gmask, w, base + j);
            int sj = __shfl_sync(gmask, s, base + j);
            float4 hv = h4[(size_t)sj * F4 + li];
            acc.x = fmaf(wj, hv.x, acc.x);
            acc.y = fmaf(wj, hv.y, acc.y);
            acc.z = fmaf(wj, hv.z, acc.z);
            acc.w = fmaf(wj, hv.w, acc.w);
        }
    }
#pragma unroll
    for (int o = F4 / 2; o > 0; o >>= 1) den += __shfl_xor_sync(gmask, den, o);

    if (d < N) {
        float r = __frcp_rn(den);
        float4 b4 = reinterpret_cast<const float4*>(bias)[li];
        float4 v;
        v.x = fmaf(acc.x, r, b4.x);
        v.y = fmaf(acc.y, r, b4.y);
        v.z = fmaf(acc.z, r, b4.z);
        v.w = fmaf(acc.w, r, b4.w);
        if (RELU) {
            v.x = fmaxf(v.x, 0.f); v.y = fmaxf(v.y, 0.f);
            v.z = fmaxf(v.z, 0.f); v.w = fmaxf(v.w, 0.f);
        }
        reinterpret_cast<float4*>(out)[(size_t)d * F4 + li] = v;
    }
}

// ---------------- launch ----------------
extern "C" void kernel_launch(void* const* d_in, const int* in_sizes, int n_in,
                              void* d_out, int out_size) {
    const float* X     = (const float*)d_in[0];
    const int*   EI    = (const int*)d_in[1];
    const float* W1    = (const float*)d_in[2];
    const float* asrc1 = (const float*)d_in[3];
    const float* adst1 = (const float*)d_in[4];
    const float* b1    = (const float*)d_in[5];
    const float* W2    = (const float*)d_in[6];
    const float* asrc2 = (const float*)d_in[7];
    const float* adst2 = (const float*)d_in[8];
    const float* b2    = (const float*)d_in[9];
    float* out = (float*)d_out;

    const int F_IN = 128;
    const int N = in_sizes[0] / F_IN;
    const int E = in_sizes[1] / 2;
    const int ET = E + N;
    const int* src = EI;
    const int* dst = EI + E;

    float *p_h, *p_x2;
    int *p_deg;
    cudaGetSymbolAddress((void**)&p_h, g_h);
    cudaGetSymbolAddress((void**)&p_x2, g_x2);
    cudaGetSymbolAddress((void**)&p_deg, g_deg);

    const int BT = 256;
    const int nb = (N + 1023) / 1024;
    const int gB1 = (N + 127) / 128;
    const int e4T = (E >> 2) + (ET - (E & ~3));

    static cudaStream_t s2 = nullptr;
    static cudaEvent_t evFork = nullptr, evJoin = nullptr;
    if (s2 == nullptr) {
        cudaStreamCreateWithFlags(&s2, cudaStreamNonBlocking);
        cudaEventCreateWithFlags(&evFork, cudaEventDisableTiming);
        cudaEventCreateWithFlags(&evJoin, cudaEventDisableTiming);
    }

    // ---- fork: CSR build on s2, GEMM1 on main stream ----
    cudaEventRecord(evFork, 0);
    cudaStreamWaitEvent(s2, evFork, 0);

    cudaMemsetAsync(p_deg, 0, (size_t)N * sizeof(int), s2);
    hist_kernel<<<(e4T + BT - 1) / BT, BT, 0, s2>>>(dst, E, ET);
    scan_partial_kernel<<<nb, 1024, 0, s2>>>(N);
    scan_final_kernel<<<nb, 1024, 0, s2>>>(N, nb);
    fill_kernel<<<(e4T + BT - 1) / BT, BT, 0, s2>>>(src, dst, E, ET);
    cudaEventRecord(evJoin, s2);

    // GEMM1 (+alpha1), tensor cores, concurrent with CSR build
    gemm_mma_alpha_kernel<128><<<gB1, BT>>>(X, W1, p_h, asrc1, adst1, N, F_IN);

    // ---- join ----
    cudaStreamWaitEvent(0, evJoin, 0);

    // gather layer 1 -> x2 (relu)
    gather_kernel<32, true><<<(N * 32 + BT - 1) / BT, BT>>>(p_h, b1, p_x2, N);

    // GEMM2 (+alpha2), tensor cores
    gemm_mma_alpha_kernel<64><<<gB1, BT>>>(p_x2, W2, p_h, asrc2, adst2, N, 128);

    // gather layer 2 -> out
    {
        long warps = (N + 1) / 2;
        gather_kernel<16, false><<<(unsigned)((warps * 32 + BT - 1) / BT), BT>>>(p_h, b2, out, N);
    }
}